// round 4
// baseline (speedup 1.0000x reference)
#include <cuda_runtime.h>
#include <math.h>

#define T_SEQ 4096
#define C_DIM 1024
#define NH    16
#define HD    64

// ---------------- scratch (static device allocations, allowed) ----------------
__device__ float g_qkv[(size_t)T_SEQ * 3 * C_DIM];   // 50.3 MB
__device__ float g_Q[(size_t)NH * T_SEQ * HD];       // 16.8 MB (head-major, RoPE'd)
__device__ float g_K[(size_t)NH * T_SEQ * HD];
__device__ float g_V[(size_t)NH * T_SEQ * HD];
__device__ float g_Y[(size_t)T_SEQ * C_DIM];         // attention output, [t][c]
__device__ float g_invf[32];

// ---------------- inv_freq table (double-accurate, matches fp32 reference) ----
__global__ void init_invfreq_kernel() {
    int j = threadIdx.x;  // 0..31
    if (j < 32) {
        double e = (double)(2 * j) / 64.0;
        g_invf[j] = (float)exp(-e * log(10000.0));
    }
}

// ---------------- SGEMM: C[M,N] = A[M,K] @ B[K,N] + bias[N] -------------------
// BM=BN=128, BK=16, 256 threads, 8x8 per thread.
__global__ __launch_bounds__(256, 2)
void sgemm_bias_kernel(const float* __restrict__ A, const float* __restrict__ B,
                       const float* __restrict__ bias, float* __restrict__ C,
                       int M, int N, int K)
{
    __shared__ float As[16][132];   // transposed A tile [k][m]
    __shared__ float Bs[16][132];   // B tile [k][n]

    int tid  = threadIdx.x;
    int row0 = blockIdx.y * 128;
    int col0 = blockIdx.x * 128;

    int aRow = tid >> 2;            // 0..63 (and +64)
    int aCol = (tid & 3) << 2;      // 0,4,8,12
    int bRow = tid >> 5;            // 0..7 (and +8)
    int bCol = (tid & 31) << 2;     // 0..124

    const float* Ap = A + (size_t)(row0 + aRow) * K + aCol;
    const float* Bp = B + (size_t)bRow * N + col0 + bCol;

    int ty = tid >> 4, tx = tid & 15;

    float acc[8][8];
#pragma unroll
    for (int i = 0; i < 8; i++)
#pragma unroll
        for (int j = 0; j < 8; j++) acc[i][j] = 0.f;

    for (int k0 = 0; k0 < K; k0 += 16) {
        float4 a0 = *(const float4*)Ap;
        float4 a1 = *(const float4*)(Ap + (size_t)64 * K);
        float4 b0 = *(const float4*)Bp;
        float4 b1 = *(const float4*)(Bp + (size_t)8 * N);

        As[aCol + 0][aRow]      = a0.x;
        As[aCol + 1][aRow]      = a0.y;
        As[aCol + 2][aRow]      = a0.z;
        As[aCol + 3][aRow]      = a0.w;
        As[aCol + 0][aRow + 64] = a1.x;
        As[aCol + 1][aRow + 64] = a1.y;
        As[aCol + 2][aRow + 64] = a1.z;
        As[aCol + 3][aRow + 64] = a1.w;
        *(float4*)&Bs[bRow][bCol]     = b0;
        *(float4*)&Bs[bRow + 8][bCol] = b1;
        __syncthreads();

#pragma unroll
        for (int k = 0; k < 16; k++) {
            float ra[8], rb[8];
            *(float4*)&ra[0] = *(const float4*)&As[k][ty * 8];
            *(float4*)&ra[4] = *(const float4*)&As[k][ty * 8 + 4];
            *(float4*)&rb[0] = *(const float4*)&Bs[k][tx * 8];
            *(float4*)&rb[4] = *(const float4*)&Bs[k][tx * 8 + 4];
#pragma unroll
            for (int i = 0; i < 8; i++)
#pragma unroll
                for (int j = 0; j < 8; j++)
                    acc[i][j] = fmaf(ra[i], rb[j], acc[i][j]);
        }
        __syncthreads();
        Ap += 16;
        Bp += (size_t)16 * N;
    }

    float bv[8];
#pragma unroll
    for (int j = 0; j < 8; j++) bv[j] = bias[col0 + tx * 8 + j];

#pragma unroll
    for (int i = 0; i < 8; i++) {
        int row = row0 + ty * 8 + i;
        float4 w0 = make_float4(acc[i][0] + bv[0], acc[i][1] + bv[1],
                                acc[i][2] + bv[2], acc[i][3] + bv[3]);
        float4 w1 = make_float4(acc[i][4] + bv[4], acc[i][5] + bv[5],
                                acc[i][6] + bv[6], acc[i][7] + bv[7]);
        *(float4*)&C[(size_t)row * N + col0 + tx * 8]     = w0;
        *(float4*)&C[(size_t)row * N + col0 + tx * 8 + 4] = w1;
    }
}

// ---------------- RoPE + split/transpose to head-major ------------------------
// out[d] = x[d]*cos(th_d) + rot(x)[d]*sin(th_d),
// rot[2i]=-x[2i+1], rot[2i+1]=x[2i], th_d = t * inv_freq[d mod 32]
__device__ __forceinline__ float reduce_2pi(float theta) {
    // reduce mod 2*pi in double so sinf/cosf see |x|<=pi (safe under fast-math)
    double k = nearbyint((double)theta * 0.15915494309189535);  // 1/(2*pi)
    return (float)((double)theta - k * 6.283185307179586);
}

__global__ void rope_split_kernel() {
    int idx = blockIdx.x * blockDim.x + threadIdx.x;
    if (idx >= T_SEQ * NH * 32) return;
    int i = idx & 31;
    int h = (idx >> 5) & 15;
    int t = idx >> 9;
    int d0 = 2 * i, d1 = d0 + 1;
    int j0 = (d0 < 32) ? d0 : d0 - 32;
    int j1 = (d1 < 32) ? d1 : d1 - 32;

    float th0 = (float)t * g_invf[j0];   // fp32, matches reference rounding
    float th1 = (float)t * g_invf[j1];
    float r0 = reduce_2pi(th0), r1 = reduce_2pi(th1);
    float s0, c0, s1, c1;
    sincosf(r0, &s0, &c0);
    sincosf(r1, &s1, &c1);

    const float* src = g_qkv + (size_t)t * (3 * C_DIM) + h * HD;
    float q0 = src[d0],            q1 = src[d1];
    float k0 = src[C_DIM + d0],    k1 = src[C_DIM + d1];
    float v0 = src[2 * C_DIM + d0], v1 = src[2 * C_DIM + d1];

    size_t dst = ((size_t)h * T_SEQ + t) * HD;
    g_Q[dst + d0] = q0 * c0 - q1 * s0;
    g_Q[dst + d1] = q1 * c1 + q0 * s1;
    g_K[dst + d0] = k0 * c0 - k1 * s0;
    g_K[dst + d1] = k1 * c1 + k0 * s1;
    g_V[dst + d0] = v0;
    g_V[dst + d1] = v1;
}

// ---------------- Flash attention (fp32, causal, online softmax) --------------
// Br=128 query rows per block, Bc=64 keys per tile, 256 threads.
struct FlashSmem {
    float Qt[64][132];   // [d][q] transposed Q tile
    float Kt[64][68];    // [d][k] transposed K tile
    float Vs[64][68];    // [k][d]
    float Ss[128][65];   // scores / probabilities
    float mS[128];
    float lS[128];
    float aS[128];
};

__global__ __launch_bounds__(256, 2)
void flash_kernel() {
    extern __shared__ char smraw[];
    FlashSmem& sm = *reinterpret_cast<FlashSmem*>(smraw);

    int tid = threadIdx.x;
    int h   = blockIdx.y;
    int qt  = (int)gridDim.x - 1 - (int)blockIdx.x;  // heavy tiles first

    const float* Qg = g_Q + ((size_t)h * T_SEQ + qt * 128) * HD;

    // load Q tile transposed: [128][64] -> Qt[d][q]
    for (int r = tid; r < 128 * 16; r += 256) {
        int q = r >> 4, dv = (r & 15) << 2;
        float4 v = *(const float4*)(Qg + (size_t)q * HD + dv);
        sm.Qt[dv + 0][q] = v.x;
        sm.Qt[dv + 1][q] = v.y;
        sm.Qt[dv + 2][q] = v.z;
        sm.Qt[dv + 3][q] = v.w;
    }
    if (tid < 128) { sm.mS[tid] = -1e30f; sm.lS[tid] = 0.f; }

    float o[4][8];
#pragma unroll
    for (int i = 0; i < 4; i++)
#pragma unroll
        for (int j = 0; j < 8; j++) o[i][j] = 0.f;
    __syncthreads();

    int ntiles = 2 * qt + 2;
    int sq = (tid >> 4) << 3, sk = (tid & 15) << 2;   // S-gemm tile: 8q x 4k
    int oq = (tid >> 3) << 2, od = (tid & 7) << 3;    // PV tile: 4q x 8d

    for (int j = 0; j < ntiles; j++) {
        const float* Kg = g_K + ((size_t)h * T_SEQ + j * 64) * HD;
        const float* Vg = g_V + ((size_t)h * T_SEQ + j * 64) * HD;
        for (int r = tid; r < 64 * 16; r += 256) {
            int kk = r >> 4, dv = (r & 15) << 2;
            float4 kv = *(const float4*)(Kg + (size_t)kk * HD + dv);
            sm.Kt[dv + 0][kk] = kv.x;
            sm.Kt[dv + 1][kk] = kv.y;
            sm.Kt[dv + 2][kk] = kv.z;
            sm.Kt[dv + 3][kk] = kv.w;
            *(float4*)&sm.Vs[kk][dv] = *(const float4*)(Vg + (size_t)kk * HD + dv);
        }
        __syncthreads();

        // S = Q @ K^T
        float s[8][4];
#pragma unroll
        for (int i = 0; i < 8; i++)
#pragma unroll
            for (int jj = 0; jj < 4; jj++) s[i][jj] = 0.f;

#pragma unroll 8
        for (int d = 0; d < 64; d++) {
            float ra[8], rb[4];
            *(float4*)&ra[0] = *(const float4*)&sm.Qt[d][sq];
            *(float4*)&ra[4] = *(const float4*)&sm.Qt[d][sq + 4];
            *(float4*)&rb[0] = *(const float4*)&sm.Kt[d][sk];
#pragma unroll
            for (int i = 0; i < 8; i++)
#pragma unroll
                for (int jj = 0; jj < 4; jj++)
                    s[i][jj] = fmaf(ra[i], rb[jj], s[i][jj]);
        }

        int gq = qt * 128 + sq, gk = j * 64 + sk;
#pragma unroll
        for (int i = 0; i < 8; i++)
#pragma unroll
            for (int jj = 0; jj < 4; jj++) {
                float val = s[i][jj] * 0.125f;             // 1/sqrt(64)
                if (gk + jj > gq + i) val = -1e30f;        // causal mask
                sm.Ss[sq + i][sk + jj] = val;
            }
        __syncthreads();

        // online softmax: 2 threads per row (32 cols each)
        {
            int row = tid >> 1, half = tid & 1, cb = half << 5;
            float mloc = -1e30f;
#pragma unroll
            for (int c = 0; c < 32; c++) mloc = fmaxf(mloc, sm.Ss[row][cb + c]);
            mloc = fmaxf(mloc, __shfl_xor_sync(0xffffffffu, mloc, 1));
            float mold = sm.mS[row];
            float mnew = fmaxf(mold, mloc);
            float sum = 0.f;
#pragma unroll
            for (int c = 0; c < 32; c++) {
                float p = __expf(sm.Ss[row][cb + c] - mnew);
                sm.Ss[row][cb + c] = p;
                sum += p;
            }
            sum += __shfl_xor_sync(0xffffffffu, sum, 1);
            if (!half) {
                sm.aS[row] = __expf(mold - mnew);
                sm.mS[row] = mnew;
                sm.lS[row] = sm.lS[row] * __expf(mold - mnew) + sum;
            }
        }
        __syncthreads();

        // O = O*alpha + P @ V
        float al[4];
#pragma unroll
        for (int i = 0; i < 4; i++) al[i] = sm.aS[oq + i];
#pragma unroll
        for (int i = 0; i < 4; i++)
#pragma unroll
            for (int jj = 0; jj < 8; jj++) o[i][jj] *= al[i];

#pragma unroll 8
        for (int k = 0; k < 64; k++) {
            float rp[4], rv[8];
#pragma unroll
            for (int i = 0; i < 4; i++) rp[i] = sm.Ss[oq + i][k];
            *(float4*)&rv[0] = *(const float4*)&sm.Vs[k][od];
            *(float4*)&rv[4] = *(const float4*)&sm.Vs[k][od + 4];
#pragma unroll
            for (int i = 0; i < 4; i++)
#pragma unroll
                for (int jj = 0; jj < 8; jj++)
                    o[i][jj] = fmaf(rp[i], rv[jj], o[i][jj]);
        }
        __syncthreads();
    }

    // epilogue: O / l, write to y[t][h*64+d]
    float linv[4];
#pragma unroll
    for (int i = 0; i < 4; i++) linv[i] = 1.f / sm.lS[oq + i];
#pragma unroll
    for (int i = 0; i < 4; i++) {
        int t = qt * 128 + oq + i;
        float4 w0 = make_float4(o[i][0] * linv[i], o[i][1] * linv[i],
                                o[i][2] * linv[i], o[i][3] * linv[i]);
        float4 w1 = make_float4(o[i][4] * linv[i], o[i][5] * linv[i],
                                o[i][6] * linv[i], o[i][7] * linv[i]);
        *(float4*)&g_Y[(size_t)t * C_DIM + h * HD + od]     = w0;
        *(float4*)&g_Y[(size_t)t * C_DIM + h * HD + od + 4] = w1;
    }
}

// ---------------- launch ------------------------------------------------------
extern "C" void kernel_launch(void* const* d_in, const int* in_sizes, int n_in,
                              void* d_out, int out_size)
{
    const float* x     = (const float*)d_in[0];
    const float* Wqkv  = (const float*)d_in[1];
    const float* bqkv  = (const float*)d_in[2];
    const float* Wproj = (const float*)d_in[3];
    const float* bproj = (const float*)d_in[4];
    float* out = (float*)d_out;

    float *qkv_p, *Y_p;
    cudaGetSymbolAddress((void**)&qkv_p, g_qkv);
    cudaGetSymbolAddress((void**)&Y_p, g_Y);

    init_invfreq_kernel<<<1, 32>>>();

    // qkv = x @ Wqkv + bqkv
    dim3 g1(3 * C_DIM / 128, T_SEQ / 128);
    sgemm_bias_kernel<<<g1, 256>>>(x, Wqkv, bqkv, qkv_p, T_SEQ, 3 * C_DIM, C_DIM);

    // rope + split to head-major Q/K/V
    rope_split_kernel<<<(T_SEQ * NH * 32) / 256, 256>>>();

    // flash attention
    static_assert(sizeof(FlashSmem) <= 110 * 1024, "smem too big");
    cudaFuncSetAttribute(flash_kernel, cudaFuncAttributeMaxDynamicSharedMemorySize,
                         (int)sizeof(FlashSmem));
    dim3 g2(T_SEQ / 128, NH);
    flash_kernel<<<g2, 256, sizeof(FlashSmem)>>>();

    // out = y @ Wproj + bproj
    dim3 g3(C_DIM / 128, T_SEQ / 128);
    sgemm_bias_kernel<<<g3, 256>>>(Y_p, Wproj, bproj, out, T_SEQ, C_DIM, C_DIM);
}

// round 6
// speedup vs baseline: 1.2529x; 1.2529x over previous
#include <cuda_runtime.h>
#include <cuda_bf16.h>
#include <math.h>
#include <stdint.h>

#define T_SEQ 4096
#define C_DIM 1024
#define NH    16
#define HD    64
#define KDIM  1024

// ---------------- scratch (static device arrays, allowed) ---------------------
__device__ float g_qkv[(size_t)T_SEQ * 3 * C_DIM];
__device__ float g_Q[(size_t)NH * T_SEQ * HD];
__device__ float g_K[(size_t)NH * T_SEQ * HD];
__device__ float g_V[(size_t)NH * T_SEQ * HD];
__device__ float g_Y[(size_t)T_SEQ * C_DIM];
__device__ float g_invf[32];
// bf16 split operands, plain row-major [rows][K]
__device__ __nv_bfloat16 g_Ahi[(size_t)T_SEQ * KDIM];
__device__ __nv_bfloat16 g_Alo[(size_t)T_SEQ * KDIM];
__device__ __nv_bfloat16 g_Bhi[(size_t)3 * C_DIM * KDIM];
__device__ __nv_bfloat16 g_Blo[(size_t)3 * C_DIM * KDIM];

// ---------------- helpers ------------------------------------------------------
__device__ __forceinline__ uint32_t smem_u32(const void* p) {
    uint32_t a;
    asm("{ .reg .u64 t; cvta.to.shared.u64 t, %1; cvt.u32.u64 %0, t; }"
        : "=r"(a) : "l"(p));
    return a;
}
__device__ __forceinline__ void cp16(uint32_t dst, const void* src) {
    asm volatile("cp.async.cg.shared.global [%0], [%1], 16;"
                 :: "r"(dst), "l"(src));
}
#define CP_COMMIT()  asm volatile("cp.async.commit_group;" ::: "memory")
#define CP_WAIT1()   asm volatile("cp.async.wait_group 1;" ::: "memory")
#define CP_WAITALL() asm volatile("cp.async.wait_all;" ::: "memory")

#define LDSM4(r, addr)                                                          \
    asm volatile("ldmatrix.sync.aligned.m8n8.x4.shared.b16 {%0,%1,%2,%3}, [%4];"\
                 : "=r"((r)[0]), "=r"((r)[1]), "=r"((r)[2]), "=r"((r)[3])       \
                 : "r"(addr))

#define MMA16816(c, a, b0, b1)                                                  \
    asm volatile("mma.sync.aligned.m16n8k16.row.col.f32.bf16.bf16.f32 "         \
                 "{%0,%1,%2,%3}, {%4,%5,%6,%7}, {%8,%9}, {%0,%1,%2,%3};"        \
                 : "+f"((c)[0]), "+f"((c)[1]), "+f"((c)[2]), "+f"((c)[3])       \
                 : "r"((a)[0]), "r"((a)[1]), "r"((a)[2]), "r"((a)[3]),          \
                   "r"(b0), "r"(b1))

// 16B-chunk XOR swizzle within a [rows][64B] tile: conflict-free ldmatrix
__device__ __forceinline__ uint32_t swz(uint32_t row, uint32_t kb) {
    return row * 64u + (kb ^ (((row >> 1) & 3u) << 4));
}

// ---------------- inv_freq table ----------------------------------------------
__global__ void init_invfreq_kernel() {
    int j = threadIdx.x;
    if (j < 32) {
        double e = (double)(2 * j) / 64.0;
        g_invf[j] = (float)exp(-e * log(10000.0));
    }
}

// ---------------- fp32 -> bf16 hi/lo split (row-major) -------------------------
__global__ void split_kernel(const float* __restrict__ src,
                             __nv_bfloat16* __restrict__ hi,
                             __nv_bfloat16* __restrict__ lo, int total) {
    int idx = blockIdx.x * blockDim.x + threadIdx.x;
    if (idx >= total) return;
    int m = idx >> 7;
    int k0 = (idx & 127) * 8;
    float4 a = *(const float4*)(src + (size_t)m * KDIM + k0);
    float4 b = *(const float4*)(src + (size_t)m * KDIM + k0 + 4);
    float v[8] = {a.x, a.y, a.z, a.w, b.x, b.y, b.z, b.w};
    __nv_bfloat16 h[8], l[8];
#pragma unroll
    for (int j = 0; j < 8; j++) {
        h[j] = __float2bfloat16(v[j]);
        l[j] = __float2bfloat16(v[j] - __bfloat162float(h[j]));
    }
    *(uint4*)(hi + (size_t)m * KDIM + k0) = *(uint4*)h;
    *(uint4*)(lo + (size_t)m * KDIM + k0) = *(uint4*)l;
}

// ---------------- W [K,N] -> Bt [N,K] bf16 hi/lo -------------------------------
__global__ void transpose_split_kernel(const float* __restrict__ W,
                                       __nv_bfloat16* __restrict__ hi,
                                       __nv_bfloat16* __restrict__ lo, int N) {
    __shared__ float s[32][33];
    int n0 = blockIdx.x * 32, k0 = blockIdx.y * 32;
    int t = threadIdx.x;
#pragma unroll
    for (int i = 0; i < 4; i++) {
        int e = t + i * 256;
        int kl = e >> 5, nl = e & 31;
        s[kl][nl] = W[(size_t)(k0 + kl) * N + n0 + nl];
    }
    __syncthreads();
    if (t < 128) {
        int nl = t >> 2, kg = t & 3, kl0 = kg * 8;
        int n = n0 + nl, k = k0 + kl0;
        __nv_bfloat16 h[8], l[8];
#pragma unroll
        for (int j = 0; j < 8; j++) {
            float v = s[kl0 + j][nl];
            h[j] = __float2bfloat16(v);
            l[j] = __float2bfloat16(v - __bfloat162float(h[j]));
        }
        *(uint4*)(hi + (size_t)n * KDIM + k) = *(uint4*)h;
        *(uint4*)(lo + (size_t)n * KDIM + k) = *(uint4*)l;
    }
}

// ---------------- mma.sync GEMM: C[M,N] = A@B + bias ---------------------------
// BM=128, BN=64, BK=32, 256 threads (8 warps 4Mx2N), 3-stage cp.async pipeline.
#define GBM 128
#define GBN 64
#define GBK 32
#define G_STAGES 3
#define G_STAGE_BYTES 24576   // Ahi 8K | Alo 8K | Bhi 4K | Blo 4K
#define G_SMEM (G_STAGES * G_STAGE_BYTES + 1024)

__global__ __launch_bounds__(256, 2)
void mma_gemm_kernel(const __nv_bfloat16* __restrict__ Ahi,
                     const __nv_bfloat16* __restrict__ Alo,
                     const __nv_bfloat16* __restrict__ Bhi,
                     const __nv_bfloat16* __restrict__ Blo,
                     const float* __restrict__ bias,
                     float* __restrict__ C, int N)
{
    extern __shared__ char sraw[];
    char* smp = (char*)(((uintptr_t)sraw + 1023) & ~(uintptr_t)1023);
    uint32_t sb = smem_u32(smp);

    int tid = threadIdx.x, lane = tid & 31, w = tid >> 5;
    int m0 = blockIdx.y * GBM, n0 = blockIdx.x * GBN;
    int mw = (w >> 1) * 32, nw = (w & 1) * 32;

    const char* gA[2] = {(const char*)(Ahi + (size_t)m0 * KDIM),
                         (const char*)(Alo + (size_t)m0 * KDIM)};
    const char* gB[2] = {(const char*)(Bhi + (size_t)n0 * KDIM),
                         (const char*)(Blo + (size_t)n0 * KDIM)};

    // per-thread load slots
    int arow0 = tid >> 2,          akch0 = tid & 3;           // A chunk tid
    int arow1 = (tid + 256) >> 2,  akch1 = tid & 3;           // A chunk tid+256
    int brow  = tid >> 2,          bkch  = tid & 3;           // B chunk tid (row 0..63)

    auto load_stage = [&](int kc, int s) {
        uint32_t base = sb + (uint32_t)s * G_STAGE_BYTES;
        size_t gk = (size_t)kc * 64;
#pragma unroll
        for (int h = 0; h < 2; h++) {
            cp16(base + h * 8192 + swz(arow0, akch0 * 16),
                 gA[h] + (size_t)arow0 * (KDIM * 2) + gk + akch0 * 16);
            cp16(base + h * 8192 + swz(arow1, akch1 * 16),
                 gA[h] + (size_t)arow1 * (KDIM * 2) + gk + akch1 * 16);
            cp16(base + 16384 + h * 4096 + swz(brow, bkch * 16),
                 gB[h] + (size_t)brow * (KDIM * 2) + gk + bkch * 16);
        }
        CP_COMMIT();
    };

    float acc[2][4][4];
#pragma unroll
    for (int i = 0; i < 2; i++)
#pragma unroll
        for (int j = 0; j < 4; j++)
#pragma unroll
            for (int k = 0; k < 4; k++) acc[i][j][k] = 0.f;

    const int KITERS = KDIM / GBK;   // 32
    load_stage(0, 0);
    load_stage(1, 1);

    for (int kc = 0; kc < KITERS; kc++) {
        CP_WAIT1();
        __syncthreads();
        if (kc + 2 < KITERS) load_stage(kc + 2, (kc + 2) % G_STAGES);
        else CP_COMMIT();

        uint32_t sbase = sb + (uint32_t)(kc % G_STAGES) * G_STAGE_BYTES;
#pragma unroll
        for (int ks = 0; ks < 2; ks++) {
            uint32_t ah[2][4], al[2][4], bh[2][4], bl[2][4];
            int kbA = ks * 32 + ((lane >> 4) << 4);
#pragma unroll
            for (int mt = 0; mt < 2; mt++) {
                int row = mw + mt * 16 + (lane & 7) + (((lane >> 3) & 1) << 3);
                uint32_t a = sbase + swz(row, kbA);
                LDSM4(ah[mt], a);
                LDSM4(al[mt], a + 8192);
            }
            int kbB = ks * 32 + (((lane >> 3) & 1) << 4);
#pragma unroll
            for (int p = 0; p < 2; p++) {
                int row = nw + p * 16 + (lane & 7) + (((lane >> 4) & 1) << 3);
                uint32_t a = sbase + 16384 + swz(row, kbB);
                LDSM4(bh[p], a);
                LDSM4(bl[p], a + 4096);
            }
#pragma unroll
            for (int mt = 0; mt < 2; mt++)
#pragma unroll
                for (int nt = 0; nt < 4; nt++) {
                    int p = nt >> 1, q = (nt & 1) * 2;
                    MMA16816(acc[mt][nt], ah[mt], bh[p][q], bh[p][q + 1]);
                    MMA16816(acc[mt][nt], ah[mt], bl[p][q], bl[p][q + 1]);
                    MMA16816(acc[mt][nt], al[mt], bh[p][q], bh[p][q + 1]);
                }
        }
    }
    CP_WAITALL();

    // epilogue: accum layout c0,c1=(row, col/col+1), c2,c3=(row+8)
#pragma unroll
    for (int mt = 0; mt < 2; mt++)
#pragma unroll
        for (int nt = 0; nt < 4; nt++) {
            int row = m0 + mw + mt * 16 + (lane >> 2);
            int col = n0 + nw + nt * 8 + 2 * (lane & 3);
            float b0 = bias[col], b1 = bias[col + 1];
            float2 v0 = make_float2(acc[mt][nt][0] + b0, acc[mt][nt][1] + b1);
            float2 v1 = make_float2(acc[mt][nt][2] + b0, acc[mt][nt][3] + b1);
            *(float2*)(C + (size_t)row * N + col)       = v0;
            *(float2*)(C + (size_t)(row + 8) * N + col) = v1;
        }
}

// ---------------- RoPE + split/transpose to head-major -------------------------
__device__ __forceinline__ float reduce_2pi(float theta) {
    double k = nearbyint((double)theta * 0.15915494309189535);
    return (float)((double)theta - k * 6.283185307179586);
}

__global__ void rope_split_kernel() {
    int idx = blockIdx.x * blockDim.x + threadIdx.x;
    if (idx >= T_SEQ * NH * 32) return;
    int i = idx & 31;
    int h = (idx >> 5) & 15;
    int t = idx >> 9;
    int d0 = 2 * i, d1 = d0 + 1;
    int j0 = (d0 < 32) ? d0 : d0 - 32;
    int j1 = (d1 < 32) ? d1 : d1 - 32;

    float th0 = (float)t * g_invf[j0];
    float th1 = (float)t * g_invf[j1];
    float r0 = reduce_2pi(th0), r1 = reduce_2pi(th1);
    float s0, c0, s1, c1;
    sincosf(r0, &s0, &c0);
    sincosf(r1, &s1, &c1);

    const float* src = g_qkv + (size_t)t * (3 * C_DIM) + h * HD;
    float q0 = src[d0],             q1 = src[d1];
    float k0 = src[C_DIM + d0],     k1 = src[C_DIM + d1];
    float v0 = src[2 * C_DIM + d0], v1 = src[2 * C_DIM + d1];

    size_t dst = ((size_t)h * T_SEQ + t) * HD;
    g_Q[dst + d0] = q0 * c0 - q1 * s0;
    g_Q[dst + d1] = q1 * c1 + q0 * s1;
    g_K[dst + d0] = k0 * c0 - k1 * s0;
    g_K[dst + d1] = k1 * c1 + k0 * s1;
    g_V[dst + d0] = v0;
    g_V[dst + d1] = v1;
}

// ---------------- Flash attention (fp32, causal, online softmax) ---------------
struct FlashSmem {
    float Qt[64][132];
    float Kt[64][68];
    float Vs[64][68];
    float Ss[128][65];
    float mS[128];
    float lS[128];
    float aS[128];
};

__global__ __launch_bounds__(256, 2)
void flash_kernel() {
    extern __shared__ char smraw[];
    FlashSmem& sm = *reinterpret_cast<FlashSmem*>(smraw);

    int tid = threadIdx.x;
    int h   = blockIdx.y;
    int qt  = (int)gridDim.x - 1 - (int)blockIdx.x;

    const float* Qg = g_Q + ((size_t)h * T_SEQ + qt * 128) * HD;

    for (int r = tid; r < 128 * 16; r += 256) {
        int q = r >> 4, dv = (r & 15) << 2;
        float4 v = *(const float4*)(Qg + (size_t)q * HD + dv);
        sm.Qt[dv + 0][q] = v.x;
        sm.Qt[dv + 1][q] = v.y;
        sm.Qt[dv + 2][q] = v.z;
        sm.Qt[dv + 3][q] = v.w;
    }
    if (tid < 128) { sm.mS[tid] = -1e30f; sm.lS[tid] = 0.f; }

    float o[4][8];
#pragma unroll
    for (int i = 0; i < 4; i++)
#pragma unroll
        for (int j = 0; j < 8; j++) o[i][j] = 0.f;
    __syncthreads();

    int ntiles = 2 * qt + 2;
    int sq = (tid >> 4) << 3, sk = (tid & 15) << 2;
    int oq = (tid >> 3) << 2, od = (tid & 7) << 3;

    for (int j = 0; j < ntiles; j++) {
        const float* Kg = g_K + ((size_t)h * T_SEQ + j * 64) * HD;
        const float* Vg = g_V + ((size_t)h * T_SEQ + j * 64) * HD;
        for (int r = tid; r < 64 * 16; r += 256) {
            int kk = r >> 4, dv = (r & 15) << 2;
            float4 kv = *(const float4*)(Kg + (size_t)kk * HD + dv);
            sm.Kt[dv + 0][kk] = kv.x;
            sm.Kt[dv + 1][kk] = kv.y;
            sm.Kt[dv + 2][kk] = kv.z;
            sm.Kt[dv + 3][kk] = kv.w;
            *(float4*)&sm.Vs[kk][dv] = *(const float4*)(Vg + (size_t)kk * HD + dv);
        }
        __syncthreads();

        float s[8][4];
#pragma unroll
        for (int i = 0; i < 8; i++)
#pragma unroll
            for (int jj = 0; jj < 4; jj++) s[i][jj] = 0.f;

#pragma unroll 8
        for (int d = 0; d < 64; d++) {
            float ra[8], rb[4];
            *(float4*)&ra[0] = *(const float4*)&sm.Qt[d][sq];
            *(float4*)&ra[4] = *(const float4*)&sm.Qt[d][sq + 4];
            *(float4*)&rb[0] = *(const float4*)&sm.Kt[d][sk];
#pragma unroll
            for (int i = 0; i < 8; i++)
#pragma unroll
                for (int jj = 0; jj < 4; jj++)
                    s[i][jj] = fmaf(ra[i], rb[jj], s[i][jj]);
        }

        int gq = qt * 128 + sq, gk = j * 64 + sk;
#pragma unroll
        for (int i = 0; i < 8; i++)
#pragma unroll
            for (int jj = 0; jj < 4; jj++) {
                float val = s[i][jj] * 0.125f;
                if (gk + jj > gq + i) val = -1e30f;
                sm.Ss[sq + i][sk + jj] = val;
            }
        __syncthreads();

        {
            int row = tid >> 1, half = tid & 1, cb = half << 5;
            float mloc = -1e30f;
#pragma unroll
            for (int c = 0; c < 32; c++) mloc = fmaxf(mloc, sm.Ss[row][cb + c]);
            mloc = fmaxf(mloc, __shfl_xor_sync(0xffffffffu, mloc, 1));
            float mold = sm.mS[row];
            float mnew = fmaxf(mold, mloc);
            float sum = 0.f;
#pragma unroll
            for (int c = 0; c < 32; c++) {
                float p = __expf(sm.Ss[row][cb + c] - mnew);
                sm.Ss[row][cb + c] = p;
                sum += p;
            }
            sum += __shfl_xor_sync(0xffffffffu, sum, 1);
            if (!half) {
                sm.aS[row] = __expf(mold - mnew);
                sm.mS[row] = mnew;
                sm.lS[row] = sm.lS[row] * __expf(mold - mnew) + sum;
            }
        }
        __syncthreads();

        float al[4];
#pragma unroll
        for (int i = 0; i < 4; i++) al[i] = sm.aS[oq + i];
#pragma unroll
        for (int i = 0; i < 4; i++)
#pragma unroll
            for (int jj = 0; jj < 8; jj++) o[i][jj] *= al[i];

#pragma unroll 8
        for (int k = 0; k < 64; k++) {
            float rp[4], rv[8];
#pragma unroll
            for (int i = 0; i < 4; i++) rp[i] = sm.Ss[oq + i][k];
            *(float4*)&rv[0] = *(const float4*)&sm.Vs[k][od];
            *(float4*)&rv[4] = *(const float4*)&sm.Vs[k][od + 4];
#pragma unroll
            for (int i = 0; i < 4; i++)
#pragma unroll
                for (int jj = 0; jj < 8; jj++)
                    o[i][jj] = fmaf(rp[i], rv[jj], o[i][jj]);
        }
        __syncthreads();
    }

    float linv[4];
#pragma unroll
    for (int i = 0; i < 4; i++) linv[i] = 1.f / sm.lS[oq + i];
#pragma unroll
    for (int i = 0; i < 4; i++) {
        int t = qt * 128 + oq + i;
        float4 w0 = make_float4(o[i][0] * linv[i], o[i][1] * linv[i],
                                o[i][2] * linv[i], o[i][3] * linv[i]);
        float4 w1 = make_float4(o[i][4] * linv[i], o[i][5] * linv[i],
                                o[i][6] * linv[i], o[i][7] * linv[i]);
        *(float4*)&g_Y[(size_t)t * C_DIM + h * HD + od]     = w0;
        *(float4*)&g_Y[(size_t)t * C_DIM + h * HD + od + 4] = w1;
    }
}

// ---------------- launch ------------------------------------------------------
extern "C" void kernel_launch(void* const* d_in, const int* in_sizes, int n_in,
                              void* d_out, int out_size)
{
    const float* x     = (const float*)d_in[0];
    const float* Wqkv  = (const float*)d_in[1];
    const float* bqkv  = (const float*)d_in[2];
    const float* Wproj = (const float*)d_in[3];
    const float* bproj = (const float*)d_in[4];
    float* out = (float*)d_out;

    float *qkv_p, *Y_p;
    __nv_bfloat16 *ahi, *alo, *bhi, *blo;
    cudaGetSymbolAddress((void**)&qkv_p, g_qkv);
    cudaGetSymbolAddress((void**)&Y_p, g_Y);
    cudaGetSymbolAddress((void**)&ahi, g_Ahi);
    cudaGetSymbolAddress((void**)&alo, g_Alo);
    cudaGetSymbolAddress((void**)&bhi, g_Bhi);
    cudaGetSymbolAddress((void**)&blo, g_Blo);

    cudaFuncSetAttribute(mma_gemm_kernel,
                         cudaFuncAttributeMaxDynamicSharedMemorySize, G_SMEM);
    cudaFuncSetAttribute(flash_kernel,
                         cudaFuncAttributeMaxDynamicSharedMemorySize,
                         (int)sizeof(FlashSmem));

    init_invfreq_kernel<<<1, 32>>>();

    // ---- GEMM1: qkv = x @ Wqkv + bqkv ----
    split_kernel<<<(T_SEQ * (KDIM / 8)) / 256, 256>>>(x, ahi, alo,
                                                      T_SEQ * (KDIM / 8));
    transpose_split_kernel<<<dim3(3 * C_DIM / 32, KDIM / 32), 256>>>(
        Wqkv, bhi, blo, 3 * C_DIM);
    mma_gemm_kernel<<<dim3(3 * C_DIM / GBN, T_SEQ / GBM), 256, G_SMEM>>>(
        ahi, alo, bhi, blo, bqkv, qkv_p, 3 * C_DIM);

    // ---- RoPE + head split ----
    rope_split_kernel<<<(T_SEQ * NH * 32) / 256, 256>>>();

    // ---- flash attention (fp32) ----
    dim3 g2(T_SEQ / 128, NH);
    flash_kernel<<<g2, 256, sizeof(FlashSmem)>>>();

    // ---- GEMM2: out = y @ Wproj + bproj ----
    split_kernel<<<(T_SEQ * (KDIM / 8)) / 256, 256>>>(Y_p, ahi, alo,
                                                      T_SEQ * (KDIM / 8));
    transpose_split_kernel<<<dim3(C_DIM / 32, KDIM / 32), 256>>>(
        Wproj, bhi, blo, C_DIM);
    mma_gemm_kernel<<<dim3(C_DIM / GBN, T_SEQ / GBM), 256, G_SMEM>>>(
        ahi, alo, bhi, blo, bproj, out, C_DIM);
}

// round 7
// speedup vs baseline: 2.9395x; 2.3462x over previous
#include <cuda_runtime.h>
#include <cuda_bf16.h>
#include <math.h>
#include <stdint.h>

#define T_SEQ 4096
#define C_DIM 1024
#define NH    16
#define HD    64
#define KDIM  1024

// ---------------- scratch (static device arrays, allowed) ---------------------
__device__ float g_qkv[(size_t)T_SEQ * 3 * C_DIM];
__device__ float g_Y[(size_t)T_SEQ * C_DIM];
__device__ float g_invf[32];
// GEMM operands (bf16 split, row-major)
__device__ __nv_bfloat16 g_Ahi[(size_t)T_SEQ * KDIM];
__device__ __nv_bfloat16 g_Alo[(size_t)T_SEQ * KDIM];
__device__ __nv_bfloat16 g_Bhi[(size_t)3 * C_DIM * KDIM];
__device__ __nv_bfloat16 g_Blo[(size_t)3 * C_DIM * KDIM];
// attention operands (bf16 split)
__device__ __nv_bfloat16 g_Qhi[(size_t)NH * T_SEQ * HD];   // [h][t][d]
__device__ __nv_bfloat16 g_Qlo[(size_t)NH * T_SEQ * HD];
__device__ __nv_bfloat16 g_Khi[(size_t)NH * T_SEQ * HD];
__device__ __nv_bfloat16 g_Klo[(size_t)NH * T_SEQ * HD];
__device__ __nv_bfloat16 g_Vthi[(size_t)NH * HD * T_SEQ];  // [h][d][t]
__device__ __nv_bfloat16 g_Vtlo[(size_t)NH * HD * T_SEQ];

// ---------------- helpers ------------------------------------------------------
__device__ __forceinline__ uint32_t smem_u32(const void* p) {
    uint32_t a;
    asm("{ .reg .u64 t; cvta.to.shared.u64 t, %1; cvt.u32.u64 %0, t; }"
        : "=r"(a) : "l"(p));
    return a;
}
__device__ __forceinline__ void cp16(uint32_t dst, const void* src) {
    asm volatile("cp.async.cg.shared.global [%0], [%1], 16;"
                 :: "r"(dst), "l"(src));
}
#define CP_COMMIT()  asm volatile("cp.async.commit_group;" ::: "memory")
#define CP_WAIT1()   asm volatile("cp.async.wait_group 1;" ::: "memory")
#define CP_WAITALL() asm volatile("cp.async.wait_all;" ::: "memory")

#define LDSM4(r, addr)                                                          \
    asm volatile("ldmatrix.sync.aligned.m8n8.x4.shared.b16 {%0,%1,%2,%3}, [%4];"\
                 : "=r"((r)[0]), "=r"((r)[1]), "=r"((r)[2]), "=r"((r)[3])       \
                 : "r"(addr))

#define MMA16816(c, a, b0, b1)                                                  \
    asm volatile("mma.sync.aligned.m16n8k16.row.col.f32.bf16.bf16.f32 "         \
                 "{%0,%1,%2,%3}, {%4,%5,%6,%7}, {%8,%9}, {%0,%1,%2,%3};"        \
                 : "+f"((c)[0]), "+f"((c)[1]), "+f"((c)[2]), "+f"((c)[3])       \
                 : "r"((a)[0]), "r"((a)[1]), "r"((a)[2]), "r"((a)[3]),          \
                   "r"(b0), "r"(b1))

// swizzle for [rows][64B] tiles (GEMM path)
__device__ __forceinline__ uint32_t swz(uint32_t row, uint32_t kb) {
    return row * 64u + (kb ^ (((row >> 1) & 3u) << 4));
}
// swizzle for [rows][128B] tiles (flash path), c = 16B-chunk index 0..7
__device__ __forceinline__ uint32_t swz128(uint32_t row, uint32_t c) {
    return row * 128u + ((c ^ (row & 7u)) << 4);
}
__device__ __forceinline__ uint32_t packbf(__nv_bfloat16 a, __nv_bfloat16 b) {
    __nv_bfloat162 t;
    t.x = a; t.y = b;
    return *reinterpret_cast<uint32_t*>(&t);
}

// ---------------- inv_freq table ----------------------------------------------
__global__ void init_invfreq_kernel() {
    int j = threadIdx.x;
    if (j < 32) {
        double e = (double)(2 * j) / 64.0;
        g_invf[j] = (float)exp(-e * log(10000.0));
    }
}

// ---------------- fp32 -> bf16 hi/lo split (row-major) -------------------------
__global__ void split_kernel(const float* __restrict__ src,
                             __nv_bfloat16* __restrict__ hi,
                             __nv_bfloat16* __restrict__ lo, int total) {
    int idx = blockIdx.x * blockDim.x + threadIdx.x;
    if (idx >= total) return;
    int m = idx >> 7;
    int k0 = (idx & 127) * 8;
    float4 a = *(const float4*)(src + (size_t)m * KDIM + k0);
    float4 b = *(const float4*)(src + (size_t)m * KDIM + k0 + 4);
    float v[8] = {a.x, a.y, a.z, a.w, b.x, b.y, b.z, b.w};
    __nv_bfloat16 h[8], l[8];
#pragma unroll
    for (int j = 0; j < 8; j++) {
        h[j] = __float2bfloat16(v[j]);
        l[j] = __float2bfloat16(v[j] - __bfloat162float(h[j]));
    }
    *(uint4*)(hi + (size_t)m * KDIM + k0) = *(uint4*)h;
    *(uint4*)(lo + (size_t)m * KDIM + k0) = *(uint4*)l;
}

// ---------------- W [K,N] -> Bt [N,K] bf16 hi/lo -------------------------------
__global__ void transpose_split_kernel(const float* __restrict__ W,
                                       __nv_bfloat16* __restrict__ hi,
                                       __nv_bfloat16* __restrict__ lo, int N) {
    __shared__ float s[32][33];
    int n0 = blockIdx.x * 32, k0 = blockIdx.y * 32;
    int t = threadIdx.x;
#pragma unroll
    for (int i = 0; i < 4; i++) {
        int e = t + i * 256;
        int kl = e >> 5, nl = e & 31;
        s[kl][nl] = W[(size_t)(k0 + kl) * N + n0 + nl];
    }
    __syncthreads();
    if (t < 128) {
        int nl = t >> 2, kg = t & 3, kl0 = kg * 8;
        int n = n0 + nl, k = k0 + kl0;
        __nv_bfloat16 h[8], l[8];
#pragma unroll
        for (int j = 0; j < 8; j++) {
            float v = s[kl0 + j][nl];
            h[j] = __float2bfloat16(v);
            l[j] = __float2bfloat16(v - __bfloat162float(h[j]));
        }
        *(uint4*)(hi + (size_t)n * KDIM + k) = *(uint4*)h;
        *(uint4*)(lo + (size_t)n * KDIM + k) = *(uint4*)l;
    }
}

// ---------------- mma.sync dense GEMM (validated R6) ---------------------------
#define GBM 128
#define GBN 64
#define GBK 32
#define G_STAGES 3
#define G_STAGE_BYTES 24576
#define G_SMEM (G_STAGES * G_STAGE_BYTES + 1024)

__global__ __launch_bounds__(256, 2)
void mma_gemm_kernel(const __nv_bfloat16* __restrict__ Ahi,
                     const __nv_bfloat16* __restrict__ Alo,
                     const __nv_bfloat16* __restrict__ Bhi,
                     const __nv_bfloat16* __restrict__ Blo,
                     const float* __restrict__ bias,
                     float* __restrict__ C, int N)
{
    extern __shared__ char sraw[];
    char* smp = (char*)(((uintptr_t)sraw + 1023) & ~(uintptr_t)1023);
    uint32_t sb = smem_u32(smp);

    int tid = threadIdx.x, lane = tid & 31, w = tid >> 5;
    int m0 = blockIdx.y * GBM, n0 = blockIdx.x * GBN;
    int mw = (w >> 1) * 32, nw = (w & 1) * 32;

    const char* gA[2] = {(const char*)(Ahi + (size_t)m0 * KDIM),
                         (const char*)(Alo + (size_t)m0 * KDIM)};
    const char* gB[2] = {(const char*)(Bhi + (size_t)n0 * KDIM),
                         (const char*)(Blo + (size_t)n0 * KDIM)};

    int arow0 = tid >> 2,         akch0 = tid & 3;
    int arow1 = (tid + 256) >> 2, akch1 = tid & 3;
    int brow  = tid >> 2,         bkch  = tid & 3;

    auto load_stage = [&](int kc, int s) {
        uint32_t base = sb + (uint32_t)s * G_STAGE_BYTES;
        size_t gk = (size_t)kc * 64;
#pragma unroll
        for (int h = 0; h < 2; h++) {
            cp16(base + h * 8192 + swz(arow0, akch0 * 16),
                 gA[h] + (size_t)arow0 * (KDIM * 2) + gk + akch0 * 16);
            cp16(base + h * 8192 + swz(arow1, akch1 * 16),
                 gA[h] + (size_t)arow1 * (KDIM * 2) + gk + akch1 * 16);
            cp16(base + 16384 + h * 4096 + swz(brow, bkch * 16),
                 gB[h] + (size_t)brow * (KDIM * 2) + gk + bkch * 16);
        }
        CP_COMMIT();
    };

    float acc[2][4][4];
#pragma unroll
    for (int i = 0; i < 2; i++)
#pragma unroll
        for (int j = 0; j < 4; j++)
#pragma unroll
            for (int k = 0; k < 4; k++) acc[i][j][k] = 0.f;

    const int KITERS = KDIM / GBK;
    load_stage(0, 0);
    load_stage(1, 1);

    for (int kc = 0; kc < KITERS; kc++) {
        CP_WAIT1();
        __syncthreads();
        if (kc + 2 < KITERS) load_stage(kc + 2, (kc + 2) % G_STAGES);
        else CP_COMMIT();

        uint32_t sbase = sb + (uint32_t)(kc % G_STAGES) * G_STAGE_BYTES;
#pragma unroll
        for (int ks = 0; ks < 2; ks++) {
            uint32_t ah[2][4], al[2][4], bh[2][4], bl[2][4];
            int kbA = ks * 32 + ((lane >> 4) << 4);
#pragma unroll
            for (int mt = 0; mt < 2; mt++) {
                int row = mw + mt * 16 + (lane & 7) + (((lane >> 3) & 1) << 3);
                uint32_t a = sbase + swz(row, kbA);
                LDSM4(ah[mt], a);
                LDSM4(al[mt], a + 8192);
            }
            int kbB = ks * 32 + (((lane >> 3) & 1) << 4);
#pragma unroll
            for (int p = 0; p < 2; p++) {
                int row = nw + p * 16 + (lane & 7) + (((lane >> 4) & 1) << 3);
                uint32_t a = sbase + 16384 + swz(row, kbB);
                LDSM4(bh[p], a);
                LDSM4(bl[p], a + 4096);
            }
#pragma unroll
            for (int mt = 0; mt < 2; mt++)
#pragma unroll
                for (int nt = 0; nt < 4; nt++) {
                    int p = nt >> 1, q = (nt & 1) * 2;
                    MMA16816(acc[mt][nt], ah[mt], bh[p][q], bh[p][q + 1]);
                    MMA16816(acc[mt][nt], ah[mt], bl[p][q], bl[p][q + 1]);
                    MMA16816(acc[mt][nt], al[mt], bh[p][q], bh[p][q + 1]);
                }
        }
    }
    CP_WAITALL();

#pragma unroll
    for (int mt = 0; mt < 2; mt++)
#pragma unroll
        for (int nt = 0; nt < 4; nt++) {
            int row = m0 + mw + mt * 16 + (lane >> 2);
            int col = n0 + nw + nt * 8 + 2 * (lane & 3);
            float b0 = bias[col], b1 = bias[col + 1];
            float2 v0 = make_float2(acc[mt][nt][0] + b0, acc[mt][nt][1] + b1);
            float2 v1 = make_float2(acc[mt][nt][2] + b0, acc[mt][nt][3] + b1);
            *(float2*)(C + (size_t)row * N + col)       = v0;
            *(float2*)(C + (size_t)(row + 8) * N + col) = v1;
        }
}

// ---------------- RoPE + bf16 split + head-major / V-transpose -----------------
__device__ __forceinline__ float reduce_2pi(float theta) {
    double k = nearbyint((double)theta * 0.15915494309189535);
    return (float)((double)theta - k * 6.283185307179586);
}

__global__ __launch_bounds__(256)
void rope_qkv_kernel() {
    __shared__ float sV[64][65];
    int h = blockIdx.y, t0 = blockIdx.x * 64, tid = threadIdx.x;

    for (int e = tid; e < 2048; e += 256) {
        int tl = e >> 5, i = e & 31;
        int t = t0 + tl, d0 = 2 * i, d1 = d0 + 1;
        int j0 = (d0 < 32) ? d0 : d0 - 32;
        int j1 = (d1 < 32) ? d1 : d1 - 32;

        float th0 = (float)t * g_invf[j0];
        float th1 = (float)t * g_invf[j1];
        float r0 = reduce_2pi(th0), r1 = reduce_2pi(th1);
        float s0, c0, s1, c1;
        sincosf(r0, &s0, &c0);
        sincosf(r1, &s1, &c1);

        const float* src = g_qkv + (size_t)t * (3 * C_DIM) + h * HD;
        float q0 = src[d0],             q1 = src[d1];
        float k0 = src[C_DIM + d0],     k1 = src[C_DIM + d1];
        float v0 = src[2 * C_DIM + d0], v1 = src[2 * C_DIM + d1];

        float qa = q0 * c0 - q1 * s0, qb = q1 * c1 + q0 * s1;
        float ka = k0 * c0 - k1 * s0, kb = k1 * c1 + k0 * s1;

        __nv_bfloat16 qah = __float2bfloat16(qa);
        __nv_bfloat16 qbh = __float2bfloat16(qb);
        __nv_bfloat16 kah = __float2bfloat16(ka);
        __nv_bfloat16 kbh = __float2bfloat16(kb);
        __nv_bfloat16 qal = __float2bfloat16(qa - __bfloat162float(qah));
        __nv_bfloat16 qbl = __float2bfloat16(qb - __bfloat162float(qbh));
        __nv_bfloat16 kal = __float2bfloat16(ka - __bfloat162float(kah));
        __nv_bfloat16 kbl = __float2bfloat16(kb - __bfloat162float(kbh));

        size_t dst = ((size_t)h * T_SEQ + t) * HD + d0;
        *(uint32_t*)(g_Qhi + dst) = packbf(qah, qbh);
        *(uint32_t*)(g_Qlo + dst) = packbf(qal, qbl);
        *(uint32_t*)(g_Khi + dst) = packbf(kah, kbh);
        *(uint32_t*)(g_Klo + dst) = packbf(kal, kbl);

        sV[tl][d0] = v0;
        sV[tl][d1] = v1;
    }
    __syncthreads();
    for (int e = tid; e < 2048; e += 256) {
        int d = e >> 5, tp = (e & 31) * 2;
        float v0 = sV[tp][d], v1 = sV[tp + 1][d];
        __nv_bfloat16 h0 = __float2bfloat16(v0);
        __nv_bfloat16 h1 = __float2bfloat16(v1);
        __nv_bfloat16 l0 = __float2bfloat16(v0 - __bfloat162float(h0));
        __nv_bfloat16 l1 = __float2bfloat16(v1 - __bfloat162float(h1));
        size_t dst = ((size_t)h * HD + d) * T_SEQ + t0 + tp;
        *(uint32_t*)(g_Vthi + dst) = packbf(h0, h1);
        *(uint32_t*)(g_Vtlo + dst) = packbf(l0, l1);
    }
}

// ---------------- Flash attention, mma.sync bf16-split -------------------------
// Br=128 (8 warps x 16 rows), Bc=64, 2-stage cp.async K/Vt tiles.
#define FB_STAGE 32768     // Khi 8K | Klo 8K | Vthi 8K | Vtlo 8K
#define FB_SMEM  (2 * FB_STAGE + 1024)

__global__ __launch_bounds__(256, 2)
void flash_mma_kernel() {
    extern __shared__ char sraw[];
    char* smp = (char*)(((uintptr_t)sraw + 127) & ~(uintptr_t)127);
    uint32_t sb = smem_u32(smp);

    int tid = threadIdx.x, lane = tid & 31, w = tid >> 5;
    int h  = blockIdx.y;
    int qt = (int)gridDim.x - 1 - (int)blockIdx.x;
    int wrow = w * 16;
    int qr = lane >> 2, qc2 = 2 * (lane & 3);

    // ---- preload Q fragments (hi/lo) from global ----
    uint32_t aQh[4][4], aQl[4][4];
    {
        const __nv_bfloat16* Qh =
            g_Qhi + ((size_t)h * T_SEQ + qt * 128 + wrow + qr) * HD;
        const __nv_bfloat16* Ql =
            g_Qlo + ((size_t)h * T_SEQ + qt * 128 + wrow + qr) * HD;
#pragma unroll
        for (int ks = 0; ks < 4; ks++) {
            int k0 = ks * 16 + qc2;
            aQh[ks][0] = *(const uint32_t*)(Qh + k0);
            aQh[ks][1] = *(const uint32_t*)(Qh + 8 * HD + k0);
            aQh[ks][2] = *(const uint32_t*)(Qh + k0 + 8);
            aQh[ks][3] = *(const uint32_t*)(Qh + 8 * HD + k0 + 8);
            aQl[ks][0] = *(const uint32_t*)(Ql + k0);
            aQl[ks][1] = *(const uint32_t*)(Ql + 8 * HD + k0);
            aQl[ks][2] = *(const uint32_t*)(Ql + k0 + 8);
            aQl[ks][3] = *(const uint32_t*)(Ql + 8 * HD + k0 + 8);
        }
    }

    float o[8][4];
#pragma unroll
    for (int i = 0; i < 8; i++)
#pragma unroll
        for (int j = 0; j < 4; j++) o[i][j] = 0.f;
    float m0 = -1e30f, m1 = -1e30f, l0 = 0.f, l1 = 0.f;

    int ntiles = 2 * qt + 2;

    // cp.async stage loader: 8 chunks per thread
    int lrow = tid >> 2;       // 0..63
    int lc   = tid & 3;        // chunk 0..3 (+4)
    auto load_stage = [&](int j, int buf) {
        uint32_t base = sb + (uint32_t)buf * FB_STAGE;
        const char* kh = (const char*)g_Khi
            + ((size_t)h * T_SEQ + (size_t)j * 64 + lrow) * (HD * 2);
        const char* kl = (const char*)g_Klo
            + ((size_t)h * T_SEQ + (size_t)j * 64 + lrow) * (HD * 2);
        const char* vh = (const char*)g_Vthi
            + (((size_t)h * HD + lrow) * T_SEQ + (size_t)j * 64) * 2;
        const char* vl = (const char*)g_Vtlo
            + (((size_t)h * HD + lrow) * T_SEQ + (size_t)j * 64) * 2;
#pragma unroll
        for (int cc = lc; cc < 8; cc += 4) {
            uint32_t sw = swz128(lrow, cc);
            cp16(base + sw,         kh + cc * 16);
            cp16(base + 8192  + sw, kl + cc * 16);
            cp16(base + 16384 + sw, vh + cc * 16);
            cp16(base + 24576 + sw, vl + cc * 16);
        }
    };

    load_stage(0, 0);
    CP_COMMIT();

    for (int j = 0; j < ntiles; j++) {
        if (j + 1 < ntiles) load_stage(j + 1, (j + 1) & 1);
        CP_COMMIT();
        CP_WAIT1();
        __syncthreads();

        uint32_t st  = sb + (uint32_t)(j & 1) * FB_STAGE;
        uint32_t sKh = st, sKl = st + 8192, sVh = st + 16384, sVl = st + 24576;

        // ---- S = Q @ K^T (3-term split) ----
        float s[8][4];
#pragma unroll
        for (int i = 0; i < 8; i++)
#pragma unroll
            for (int jj = 0; jj < 4; jj++) s[i][jj] = 0.f;

#pragma unroll
        for (int ks = 0; ks < 4; ks++) {
            int rsel = (lane & 7) + (((lane >> 4) & 1) << 3);
            int c    = 2 * ks + ((lane >> 3) & 1);
#pragma unroll
            for (int p = 0; p < 4; p++) {
                uint32_t bh[4], bl[4];
                int row = p * 16 + rsel;
                uint32_t a = sKh + swz128(row, c);
                LDSM4(bh, a);
                LDSM4(bl, a + 8192);
#pragma unroll
                for (int sub = 0; sub < 2; sub++) {
                    int nt = p * 2 + sub, q = sub * 2;
                    MMA16816(s[nt], aQh[ks], bh[q], bh[q + 1]);
                    MMA16816(s[nt], aQh[ks], bl[q], bl[q + 1]);
                    MMA16816(s[nt], aQl[ks], bh[q], bh[q + 1]);
                }
            }
        }

        // ---- scale + causal mask ----
        int row0 = qt * 128 + wrow + qr;
        bool need_mask = (j >= 2 * qt);
#pragma unroll
        for (int nt = 0; nt < 8; nt++) {
            int cb = j * 64 + nt * 8 + qc2;
#pragma unroll
            for (int e = 0; e < 4; e++) {
                float v = s[nt][e] * 0.125f;
                if (need_mask) {
                    int col = cb + (e & 1);
                    int row = row0 + (e >> 1) * 8;
                    if (col > row) v = -1e30f;
                }
                s[nt][e] = v;
            }
        }

        // ---- online softmax on fragments ----
        float mx0 = -1e30f, mx1 = -1e30f;
#pragma unroll
        for (int nt = 0; nt < 8; nt++) {
            mx0 = fmaxf(mx0, fmaxf(s[nt][0], s[nt][1]));
            mx1 = fmaxf(mx1, fmaxf(s[nt][2], s[nt][3]));
        }
        mx0 = fmaxf(mx0, __shfl_xor_sync(0xffffffffu, mx0, 1));
        mx0 = fmaxf(mx0, __shfl_xor_sync(0xffffffffu, mx0, 2));
        mx1 = fmaxf(mx1, __shfl_xor_sync(0xffffffffu, mx1, 1));
        mx1 = fmaxf(mx1, __shfl_xor_sync(0xffffffffu, mx1, 2));

        float mn0 = fmaxf(m0, mx0), mn1 = fmaxf(m1, mx1);
        float a0 = __expf(m0 - mn0), a1 = __expf(m1 - mn1);
        float sum0 = 0.f, sum1 = 0.f;
#pragma unroll
        for (int nt = 0; nt < 8; nt++) {
            float p0 = __expf(s[nt][0] - mn0);
            float p1 = __expf(s[nt][1] - mn0);
            float p2 = __expf(s[nt][2] - mn1);
            float p3 = __expf(s[nt][3] - mn1);
            s[nt][0] = p0; s[nt][1] = p1; s[nt][2] = p2; s[nt][3] = p3;
            sum0 += p0 + p1;
            sum1 += p2 + p3;
        }
        sum0 += __shfl_xor_sync(0xffffffffu, sum0, 1);
        sum0 += __shfl_xor_sync(0xffffffffu, sum0, 2);
        sum1 += __shfl_xor_sync(0xffffffffu, sum1, 1);
        sum1 += __shfl_xor_sync(0xffffffffu, sum1, 2);
        l0 = l0 * a0 + sum0;
        l1 = l1 * a1 + sum1;
        m0 = mn0; m1 = mn1;
#pragma unroll
        for (int i = 0; i < 8; i++) {
            o[i][0] *= a0; o[i][1] *= a0;
            o[i][2] *= a1; o[i][3] *= a1;
        }

        // ---- repack P -> A fragments (hi/lo) ----
        uint32_t aPh[4][4], aPl[4][4];
#pragma unroll
        for (int ks = 0; ks < 4; ks++) {
#pragma unroll
            for (int half = 0; half < 2; half++) {
                int nt = 2 * ks + half;
                __nv_bfloat16 h0 = __float2bfloat16(s[nt][0]);
                __nv_bfloat16 h1 = __float2bfloat16(s[nt][1]);
                __nv_bfloat16 h2 = __float2bfloat16(s[nt][2]);
                __nv_bfloat16 h3 = __float2bfloat16(s[nt][3]);
                aPh[ks][half * 2]     = packbf(h0, h1);
                aPh[ks][half * 2 + 1] = packbf(h2, h3);
                aPl[ks][half * 2]     = packbf(
                    __float2bfloat16(s[nt][0] - __bfloat162float(h0)),
                    __float2bfloat16(s[nt][1] - __bfloat162float(h1)));
                aPl[ks][half * 2 + 1] = packbf(
                    __float2bfloat16(s[nt][2] - __bfloat162float(h2)),
                    __float2bfloat16(s[nt][3] - __bfloat162float(h3)));
            }
        }

        // ---- O += P @ V (3-term split) ----
#pragma unroll
        for (int ks = 0; ks < 4; ks++) {
            int rsel = (lane & 7) + (((lane >> 4) & 1) << 3);
            int c    = 2 * ks + ((lane >> 3) & 1);
#pragma unroll
            for (int p = 0; p < 4; p++) {
                uint32_t bh[4], bl[4];
                int row = p * 16 + rsel;
                uint32_t a = sVh + swz128(row, c);
                LDSM4(bh, a);
                LDSM4(bl, a + 8192);
                (void)sKl; (void)sVl;
#pragma unroll
                for (int sub = 0; sub < 2; sub++) {
                    int nt = p * 2 + sub, q = sub * 2;
                    MMA16816(o[nt], aPh[ks], bh[q], bh[q + 1]);
                    MMA16816(o[nt], aPh[ks], bl[q], bl[q + 1]);
                    MMA16816(o[nt], aPl[ks], bh[q], bh[q + 1]);
                }
            }
        }
        __syncthreads();
    }

    // ---- epilogue ----
    float li0 = 1.f / l0, li1 = 1.f / l1;
    int r0 = qt * 128 + wrow + qr;
    float* Y0 = g_Y + (size_t)r0 * C_DIM + h * HD;
#pragma unroll
    for (int nt = 0; nt < 8; nt++) {
        int col = nt * 8 + qc2;
        *(float2*)(Y0 + col) = make_float2(o[nt][0] * li0, o[nt][1] * li0);
        *(float2*)(Y0 + 8 * C_DIM + col) =
            make_float2(o[nt][2] * li1, o[nt][3] * li1);
    }
}

// ---------------- launch ------------------------------------------------------
extern "C" void kernel_launch(void* const* d_in, const int* in_sizes, int n_in,
                              void* d_out, int out_size)
{
    const float* x     = (const float*)d_in[0];
    const float* Wqkv  = (const float*)d_in[1];
    const float* bqkv  = (const float*)d_in[2];
    const float* Wproj = (const float*)d_in[3];
    const float* bproj = (const float*)d_in[4];
    float* out = (float*)d_out;

    float *qkv_p, *Y_p;
    __nv_bfloat16 *ahi, *alo, *bhi, *blo;
    cudaGetSymbolAddress((void**)&qkv_p, g_qkv);
    cudaGetSymbolAddress((void**)&Y_p, g_Y);
    cudaGetSymbolAddress((void**)&ahi, g_Ahi);
    cudaGetSymbolAddress((void**)&alo, g_Alo);
    cudaGetSymbolAddress((void**)&bhi, g_Bhi);
    cudaGetSymbolAddress((void**)&blo, g_Blo);

    cudaFuncSetAttribute(mma_gemm_kernel,
                         cudaFuncAttributeMaxDynamicSharedMemorySize, G_SMEM);
    cudaFuncSetAttribute(flash_mma_kernel,
                         cudaFuncAttributeMaxDynamicSharedMemorySize, FB_SMEM);

    init_invfreq_kernel<<<1, 32>>>();

    // ---- GEMM1: qkv = x @ Wqkv + bqkv ----
    split_kernel<<<(T_SEQ * (KDIM / 8)) / 256, 256>>>(x, ahi, alo,
                                                      T_SEQ * (KDIM / 8));
    transpose_split_kernel<<<dim3(3 * C_DIM / 32, KDIM / 32), 256>>>(
        Wqkv, bhi, blo, 3 * C_DIM);
    mma_gemm_kernel<<<dim3(3 * C_DIM / GBN, T_SEQ / GBM), 256, G_SMEM>>>(
        ahi, alo, bhi, blo, bqkv, qkv_p, 3 * C_DIM);

    // ---- RoPE + bf16 split + V transpose ----
    rope_qkv_kernel<<<dim3(T_SEQ / 64, NH), 256>>>();

    // ---- flash attention (mma.sync bf16-split) ----
    flash_mma_kernel<<<dim3(T_SEQ / 128, NH), 256, FB_SMEM>>>();

    // ---- GEMM2: out = y @ Wproj + bproj ----
    split_kernel<<<(T_SEQ * (KDIM / 8)) / 256, 256>>>(Y_p, ahi, alo,
                                                      T_SEQ * (KDIM / 8));
    transpose_split_kernel<<<dim3(C_DIM / 32, KDIM / 32), 256>>>(
        Wproj, bhi, blo, C_DIM);
    mma_gemm_kernel<<<dim3(C_DIM / GBN, T_SEQ / GBM), 256, G_SMEM>>>(
        ahi, alo, bhi, blo, bproj, out, C_DIM);
}